// round 15
// baseline (speedup 1.0000x reference)
#include <cuda_runtime.h>
#include <cuda_fp16.h>

#define N_NODES   200000
#define N_EDGES   3200000
#define N_GRAPHS  1024
#define CAP       64          // fixed CSR capacity per node; P(deg>=64) ~ 1e-19

// ---------------- scratch (static device globals) ---------------------------
__device__ __half g_Sh[N_NODES * 64];   // scaled activations S = h * dinv (fp16)
__device__ __half g_Uh[N_NODES * 64];   // gemm outputs (messages, fp16)
__device__ float  g_T0[N_NODES * 8];    // layer-0 aggregated input (fp32)
__device__ float  g_xs[N_NODES * 8];    // x * dinv
__device__ int    g_cur[N_NODES];       // per-node edge count (atomic cursor)
__device__ int    g_csr[N_NODES * CAP]; // fixed-capacity adjacency (src per slot)
__device__ float  g_dinv[N_NODES];
__device__ float  g_gmax[N_GRAPHS * 32];
__device__ float  g_gsum[N_GRAPHS * 32];
__device__ float  g_cnt[N_GRAPHS];
__device__ int    g_idx64;

// ---------------- prep kernels ----------------------------------------------

__global__ void init_kernel(const void* __restrict__ ei) {
    int i = blockIdx.x * blockDim.x + threadIdx.x;
    if (i == 0) {
        const long long* p = (const long long*)ei;
        int ok = 1;
#pragma unroll
        for (int k = 0; k < 16; k++) {
            long long v = p[k];
            if (v < 0 || v >= N_NODES) ok = 0;
        }
        g_idx64 = ok;
    }
    if (i < N_NODES) g_cur[i] = 0;
    if (i < N_GRAPHS * 32) { g_gmax[i] = 0.0f; g_gsum[i] = 0.0f; }
    if (i < N_GRAPHS) g_cnt[i] = 0.0f;
}

// Single-pass CSR build: count + place in one kernel.
__global__ void fill_kernel(const void* __restrict__ ei) {
    int e = blockIdx.x * blockDim.x + threadIdx.x;
    if (e >= N_EDGES) return;
    int s, d;
    if (g_idx64) {
        const long long* p = (const long long*)ei;
        s = (int)p[e]; d = (int)p[N_EDGES + e];
    } else {
        const int* p = (const int*)ei;
        s = p[e]; d = p[N_EDGES + e];
    }
    int pos = atomicAdd(&g_cur[d], 1);
    if (pos < CAP) g_csr[d * CAP + pos] = s;
}

// dinv = rsqrt(deg+1); xs = x * dinv.
__global__ void dinv_xs_kernel(const float* __restrict__ x) {
    int i = blockIdx.x * blockDim.x + threadIdx.x;
    if (i >= N_NODES) return;
    float dv = rsqrtf((float)(g_cur[i] + 1));
    g_dinv[i] = dv;
    float4 v0 = *(const float4*)(x + (size_t)i * 8);
    float4 v1 = *(const float4*)(x + (size_t)i * 8 + 4);
    v0.x *= dv; v0.y *= dv; v0.z *= dv; v0.w *= dv;
    v1.x *= dv; v1.y *= dv; v1.z *= dv; v1.w *= dv;
    *(float4*)(g_xs + (size_t)i * 8) = v0;
    *(float4*)(g_xs + (size_t)i * 8 + 4) = v1;
}

// ---------------- layer kernels ---------------------------------------------

// Width-8 input aggregation, WARP PER NODE: 4 edge-groups x 8 features.
// Group g walks edges g, g+4, g+8, ... with 2 accumulators; shfl_xor combine.
// Grid exact: N_NODES warps = 25000 blocks x 8 warps.
__global__ void agg0_kernel() {
    int gid  = blockIdx.x * blockDim.x + threadIdx.x;
    int node = gid >> 5;
    int lane = gid & 31;
    int grp  = lane >> 3;     // 0..3
    int feat = lane & 7;      // 0..7
    int dg = g_cur[node]; if (dg > CAP) dg = CAP;
    const int* crow = g_csr + node * CAP;
    float acc0 = (grp == 0) ? g_xs[(size_t)node * 8 + feat] : 0.0f;
    float acc1 = 0.0f;
    int i = grp;
    for (; i + 4 < dg; i += 8) {
        int s0 = __ldg(crow + i);
        int s1 = __ldg(crow + i + 4);
        acc0 += __ldg(&g_xs[(size_t)s0 * 8 + feat]);
        acc1 += __ldg(&g_xs[(size_t)s1 * 8 + feat]);
    }
    if (i < dg) {
        int s0 = __ldg(crow + i);
        acc0 += __ldg(&g_xs[(size_t)s0 * 8 + feat]);
    }
    float acc = acc0 + acc1;
    acc += __shfl_xor_sync(0xffffffffu, acc, 8);
    acc += __shfl_xor_sync(0xffffffffu, acc, 16);
    if (grp == 0)
        g_T0[(size_t)node * 8 + feat] = acc * g_dinv[node];
}

// Layer-0 scalar GEMM (K=8): out = tanh(t0 @ W0 + b) * dinv, fp16 out.
__global__ void gemm0_kernel(const float* __restrict__ in, const float* __restrict__ W,
                             const float* __restrict__ b, __half* __restrict__ outh) {
    const int K = 8, NO = 64, TPN = 16, NPB = 16;
    __shared__ float sW[K * NO];
    __shared__ float sIn[NPB * K];
    for (int i = threadIdx.x; i < K * NO; i += 256) sW[i] = W[i];
    int node0 = blockIdx.x * NPB;
    for (int i = threadIdx.x; i < NPB * K; i += 256) {
        int n = node0 + i / K;
        sIn[i] = (n < N_NODES) ? in[(size_t)n * K + (i % K)] : 0.0f;
    }
    __syncthreads();
    int node = node0 + threadIdx.x / TPN;
    int oc   = (threadIdx.x % TPN) * 4;
    if (node >= N_NODES) return;
    const float* r = sIn + (threadIdx.x / TPN) * K;
    float a0 = 0.f, a1 = 0.f, a2 = 0.f, a3 = 0.f;
#pragma unroll
    for (int k = 0; k < K; k++) {
        float xv = r[k];
        float4 w = *(const float4*)(sW + k * NO + oc);
        a0 += xv * w.x; a1 += xv * w.y; a2 += xv * w.z; a3 += xv * w.w;
    }
    float dv = g_dinv[node];
    float4 bb = *(const float4*)(b + oc);
    a0 = tanhf(a0 + bb.x) * dv;
    a1 = tanhf(a1 + bb.y) * dv;
    a2 = tanhf(a2 + bb.z) * dv;
    a3 = tanhf(a3 + bb.w) * dv;
    __half2 h01 = __floats2half2_rn(a0, a1);
    __half2 h23 = __floats2half2_rn(a2, a3);
    uint2 st;
    st.x = *(unsigned int*)&h01;
    st.y = *(unsigned int*)&h23;
    *(uint2*)(outh + (size_t)node * NO + oc) = st;
}

// HMMA GEMM, layers 1-3: out = in @ W, fp16 in/out, fp32 accum, split-W hi/lo.
template <int K, int NO>
__global__ void gemm_mma_kernel(const __half* __restrict__ in, const float* __restrict__ W,
                                __half* __restrict__ outh) {
    const int LDA = K + 8;
    const int LDB = NO + 8;
    const int KC = K / 16;
    const int NT = NO / 8;
    const int NPB = 128;
    __shared__ __half sA[NPB * LDA];
    __shared__ __half sBhi[K * LDB];
    __shared__ __half sBlo[K * LDB];
    int tid = threadIdx.x;
    int node0 = blockIdx.x * NPB;
    int nvalid = N_NODES - node0;
    if (nvalid > NPB) nvalid = NPB;

    for (int i = tid; i < NPB * (K / 8); i += 256) {
        int r = i / (K / 8), c = i % (K / 8);
        uint4 v = make_uint4(0u, 0u, 0u, 0u);
        if (r < nvalid)
            v = ((const uint4*)(in + (size_t)node0 * K))[i];
        *(uint4*)(sA + r * LDA + c * 8) = v;
    }
    for (int i = tid; i < K * NO / 2; i += 256) {
        int k = i / (NO / 2), n2 = i % (NO / 2);
        float2 w = ((const float2*)W)[i];
        __half hx = __float2half_rn(w.x);
        __half hy = __float2half_rn(w.y);
        __half lx = __float2half_rn(w.x - __half2float(hx));
        __half ly = __float2half_rn(w.y - __half2float(hy));
        ((__half2*)(sBhi + k * LDB))[n2] = __halves2half2(hx, hy);
        ((__half2*)(sBlo + k * LDB))[n2] = __halves2half2(lx, ly);
    }
    __syncthreads();

    int warp = tid >> 5, lane = tid & 31;
    float acc[NT][4];
#pragma unroll
    for (int nt = 0; nt < NT; nt++)
#pragma unroll
        for (int j = 0; j < 4; j++) acc[nt][j] = 0.0f;

    int a_row = warp * 16 + (lane & 15);
    int a_col = (lane >> 4) * 8;
    int b_r   = lane & 7;
    int b_m   = lane >> 3;

#pragma unroll
    for (int kc = 0; kc < KC; kc++) {
        unsigned a0, a1, a2, a3;
        {
            unsigned addr = (unsigned)__cvta_generic_to_shared(
                sA + a_row * LDA + kc * 16 + a_col);
            asm volatile("ldmatrix.sync.aligned.m8n8.x4.shared.b16 {%0,%1,%2,%3}, [%4];"
                         : "=r"(a0), "=r"(a1), "=r"(a2), "=r"(a3) : "r"(addr));
        }
        int krow = kc * 16 + b_r + ((b_m & 1) ? 8 : 0);
#pragma unroll
        for (int nt = 0; nt < NT; nt += 2) {
            int ncol = (nt + ((b_m >> 1) & 1)) * 8;
            unsigned b0, b1, b2, b3;
            {
                unsigned addr = (unsigned)__cvta_generic_to_shared(
                    sBhi + krow * LDB + ncol);
                asm volatile("ldmatrix.sync.aligned.m8n8.x4.trans.shared.b16 {%0,%1,%2,%3}, [%4];"
                             : "=r"(b0), "=r"(b1), "=r"(b2), "=r"(b3) : "r"(addr));
            }
            asm volatile("mma.sync.aligned.m16n8k16.row.col.f32.f16.f16.f32 "
                         "{%0,%1,%2,%3}, {%4,%5,%6,%7}, {%8,%9}, {%0,%1,%2,%3};"
                         : "+f"(acc[nt][0]), "+f"(acc[nt][1]), "+f"(acc[nt][2]), "+f"(acc[nt][3])
                         : "r"(a0), "r"(a1), "r"(a2), "r"(a3), "r"(b0), "r"(b1));
            asm volatile("mma.sync.aligned.m16n8k16.row.col.f32.f16.f16.f32 "
                         "{%0,%1,%2,%3}, {%4,%5,%6,%7}, {%8,%9}, {%0,%1,%2,%3};"
                         : "+f"(acc[nt+1][0]), "+f"(acc[nt+1][1]), "+f"(acc[nt+1][2]), "+f"(acc[nt+1][3])
                         : "r"(a0), "r"(a1), "r"(a2), "r"(a3), "r"(b2), "r"(b3));
            {
                unsigned addr = (unsigned)__cvta_generic_to_shared(
                    sBlo + krow * LDB + ncol);
                asm volatile("ldmatrix.sync.aligned.m8n8.x4.trans.shared.b16 {%0,%1,%2,%3}, [%4];"
                             : "=r"(b0), "=r"(b1), "=r"(b2), "=r"(b3) : "r"(addr));
            }
            asm volatile("mma.sync.aligned.m16n8k16.row.col.f32.f16.f16.f32 "
                         "{%0,%1,%2,%3}, {%4,%5,%6,%7}, {%8,%9}, {%0,%1,%2,%3};"
                         : "+f"(acc[nt][0]), "+f"(acc[nt][1]), "+f"(acc[nt][2]), "+f"(acc[nt][3])
                         : "r"(a0), "r"(a1), "r"(a2), "r"(a3), "r"(b0), "r"(b1));
            asm volatile("mma.sync.aligned.m16n8k16.row.col.f32.f16.f16.f32 "
                         "{%0,%1,%2,%3}, {%4,%5,%6,%7}, {%8,%9}, {%0,%1,%2,%3};"
                         : "+f"(acc[nt+1][0]), "+f"(acc[nt+1][1]), "+f"(acc[nt+1][2]), "+f"(acc[nt+1][3])
                         : "r"(a0), "r"(a1), "r"(a2), "r"(a3), "r"(b2), "r"(b3));
        }
    }

    int r0 = node0 + warp * 16 + (lane >> 2);
    int cbase = (lane & 3) * 2;
#pragma unroll
    for (int nt = 0; nt < NT; nt++) {
        int c = nt * 8 + cbase;
        if (r0 < N_NODES)
            *(__half2*)(outh + (size_t)r0 * NO + c) = __floats2half2_rn(acc[nt][0], acc[nt][1]);
        if (r0 + 8 < N_NODES)
            *(__half2*)(outh + (size_t)(r0 + 8) * NO + c) = __floats2half2_rn(acc[nt][2], acc[nt][3]);
    }
}

// Layer-1 aggregation (width 64): warp per node, 32 lanes x half2, 4-way unroll.
__global__ void agg_act64_kernel(const __half* __restrict__ u, const float* __restrict__ b,
                                 __half* __restrict__ out) {
    int gid  = blockIdx.x * blockDim.x + threadIdx.x;
    int node = gid >> 5;
    int lane = gid & 31;
    if (node >= N_NODES) return;
    const __half2* base = (const __half2*)u + lane;
    const size_t rowstride = 32;
    float2 a0, a1, a2, a3;
    {
        float2 f = __half22float2(__ldg(base + (size_t)node * rowstride));
        a0 = f;
        a1 = make_float2(0.f, 0.f); a2 = a1; a3 = a1;
    }
    int dg = g_cur[node]; if (dg > CAP) dg = CAP;
    const int* crow = g_csr + node * CAP;
    int i = 0;
    for (; i + 4 <= dg; i += 4) {
        int s0 = __ldg(crow + i);
        int s1 = __ldg(crow + i + 1);
        int s2 = __ldg(crow + i + 2);
        int s3 = __ldg(crow + i + 3);
        float2 f0 = __half22float2(__ldg(base + (size_t)s0 * rowstride));
        float2 f1 = __half22float2(__ldg(base + (size_t)s1 * rowstride));
        float2 f2 = __half22float2(__ldg(base + (size_t)s2 * rowstride));
        float2 f3 = __half22float2(__ldg(base + (size_t)s3 * rowstride));
        a0.x += f0.x; a0.y += f0.y;
        a1.x += f1.x; a1.y += f1.y;
        a2.x += f2.x; a2.y += f2.y;
        a3.x += f3.x; a3.y += f3.y;
    }
    for (; i < dg; i++) {
        int s0 = __ldg(crow + i);
        float2 f0 = __half22float2(__ldg(base + (size_t)s0 * rowstride));
        a0.x += f0.x; a0.y += f0.y;
    }
    float sx = (a0.x + a1.x) + (a2.x + a3.x);
    float sy = (a0.y + a1.y) + (a2.y + a3.y);
    float dv = g_dinv[node];
    float2 bb = *(const float2*)(b + lane * 2);
    float vx = fmaxf(fmaf(dv, sx, bb.x), 0.0f);
    float vy = fmaxf(fmaf(dv, sy, bb.y), 0.0f);
    __half2 h = __floats2half2_rn(vx * dv, vy * dv);
    ((__half2*)out)[(size_t)node * rowstride + lane] = h;
}

// Layer-2 aggregation (width 32): WARP PER NODE, 2 edge-groups x 16 half2 cols.
// Group g walks edges g, g+2, g+4, ... with 2 accumulators; shfl_xor(16) combine.
__global__ void agg_act32_kernel(const __half* __restrict__ u, const float* __restrict__ b,
                                 __half* __restrict__ out) {
    int gid  = blockIdx.x * blockDim.x + threadIdx.x;
    int node = gid >> 5;
    int lane = gid & 31;
    int grp  = lane >> 4;     // 0..1
    int col  = lane & 15;     // half2 column
    const __half2* base = (const __half2*)u + col;
    const size_t rowstride = 16;
    float2 a0, a1;
    if (grp == 0) {
        a0 = __half22float2(__ldg(base + (size_t)node * rowstride));
    } else {
        a0 = make_float2(0.f, 0.f);
    }
    a1 = make_float2(0.f, 0.f);
    int dg = g_cur[node]; if (dg > CAP) dg = CAP;
    const int* crow = g_csr + node * CAP;
    int i = grp;
    for (; i + 2 < dg; i += 4) {
        int s0 = __ldg(crow + i);
        int s1 = __ldg(crow + i + 2);
        float2 f0 = __half22float2(__ldg(base + (size_t)s0 * rowstride));
        float2 f1 = __half22float2(__ldg(base + (size_t)s1 * rowstride));
        a0.x += f0.x; a0.y += f0.y;
        a1.x += f1.x; a1.y += f1.y;
    }
    if (i < dg) {
        int s0 = __ldg(crow + i);
        float2 f0 = __half22float2(__ldg(base + (size_t)s0 * rowstride));
        a0.x += f0.x; a0.y += f0.y;
    }
    float sx = a0.x + a1.x;
    float sy = a0.y + a1.y;
    sx += __shfl_xor_sync(0xffffffffu, sx, 16);
    sy += __shfl_xor_sync(0xffffffffu, sy, 16);
    if (grp == 0) {
        float dv = g_dinv[node];
        float2 bb = *(const float2*)(b + col * 2);
        float vx = fmaxf(fmaf(dv, sx, bb.x), 0.0f);
        float vy = fmaxf(fmaf(dv, sy, bb.y), 0.0f);
        __half2 h = __floats2half2_rn(vx * dv, vy * dv);
        ((__half2*)out)[(size_t)node * rowstride + col] = h;
    }
}

// Layer-3 aggregation + pooling: warp per node (2 edge-groups x 16 cols) +
// block-level segmented reduction over 8 nodes (batch sorted).
__global__ void agg_pool_kernel(const __half* __restrict__ u, const float* __restrict__ b,
                                const void* __restrict__ batch) {
    __shared__ float smax[8][33];
    __shared__ float ssum[8][33];
    __shared__ int   sg[8];
    int tid  = threadIdx.x;
    int nl   = tid >> 5;      // local node 0..7
    int lane = tid & 31;
    int grp  = lane >> 4;
    int col  = lane & 15;
    int node = blockIdx.x * 8 + nl;

    const __half2* base = (const __half2*)u + col;
    const size_t rowstride = 16;
    float2 a0, a1;
    if (grp == 0) {
        a0 = __half22float2(__ldg(base + (size_t)node * rowstride));
    } else {
        a0 = make_float2(0.f, 0.f);
    }
    a1 = make_float2(0.f, 0.f);
    int dg = g_cur[node]; if (dg > CAP) dg = CAP;
    const int* crow = g_csr + node * CAP;
    int i = grp;
    for (; i + 2 < dg; i += 4) {
        int s0 = __ldg(crow + i);
        int s1 = __ldg(crow + i + 2);
        float2 f0 = __half22float2(__ldg(base + (size_t)s0 * rowstride));
        float2 f1 = __half22float2(__ldg(base + (size_t)s1 * rowstride));
        a0.x += f0.x; a0.y += f0.y;
        a1.x += f1.x; a1.y += f1.y;
    }
    if (i < dg) {
        int s0 = __ldg(crow + i);
        float2 f0 = __half22float2(__ldg(base + (size_t)s0 * rowstride));
        a0.x += f0.x; a0.y += f0.y;
    }
    float sx = a0.x + a1.x;
    float sy = a0.y + a1.y;
    sx += __shfl_xor_sync(0xffffffffu, sx, 16);
    sy += __shfl_xor_sync(0xffffffffu, sy, 16);
    if (grp == 0) {
        float dv = g_dinv[node];
        float2 bb = *(const float2*)(b + col * 2);
        float vx = fmaxf(fmaf(dv, sx, bb.x), 0.0f);
        float vy = fmaxf(fmaf(dv, sy, bb.y), 0.0f);
        smax[nl][col * 2]     = vx;
        smax[nl][col * 2 + 1] = vy;
        ssum[nl][col * 2]     = vx;
        ssum[nl][col * 2 + 1] = vy;
        if (col == 0) {
            int g;
            if (g_idx64) g = (int)((const long long*)batch)[node];
            else         g = ((const int*)batch)[node];
            sg[nl] = g;
        }
    }
    __syncthreads();

    if (tid < 32) {
        int curg = sg[0];
        float cm = smax[0][tid];
        float cs = ssum[0][tid];
#pragma unroll
        for (int k = 1; k < 8; k++) {
            int gi = sg[k];
            float m = smax[k][tid];
            float s = ssum[k][tid];
            if (gi != curg) {
                atomicMax((int*)&g_gmax[curg * 32 + tid], __float_as_int(cm));
                atomicAdd(&g_gsum[curg * 32 + tid], cs);
                curg = gi; cm = m; cs = s;
            } else {
                cm = fmaxf(cm, m);
                cs += s;
            }
        }
        atomicMax((int*)&g_gmax[curg * 32 + tid], __float_as_int(cm));
        atomicAdd(&g_gsum[curg * 32 + tid], cs);
    } else if (tid == 32) {
        int curg = sg[0];
        float c = 1.0f;
#pragma unroll
        for (int k = 1; k < 8; k++) {
            if (sg[k] != curg) {
                atomicAdd(&g_cnt[curg], c);
                curg = sg[k]; c = 1.0f;
            } else c += 1.0f;
        }
        atomicAdd(&g_cnt[curg], c);
    }
}

__global__ void final_kernel(const float* __restrict__ Wout, const float* __restrict__ bout,
                             float* __restrict__ out) {
    int idx = blockIdx.x * blockDim.x + threadIdx.x;
    if (idx >= N_GRAPHS * 10) return;
    int g = idx / 10, o = idx % 10;
    float inv = 1.0f / fmaxf(g_cnt[g], 1.0f);
    float s = bout[o];
#pragma unroll
    for (int f = 0; f < 32; f++) s = fmaf(g_gmax[g * 32 + f], Wout[f * 10 + o], s);
#pragma unroll
    for (int f = 0; f < 32; f++) s = fmaf(g_gsum[g * 32 + f] * inv, Wout[(32 + f) * 10 + o], s);
    out[idx] = s;
}

// ---------------- launch -----------------------------------------------------

extern "C" void kernel_launch(void* const* d_in, const int* in_sizes, int n_in,
                              void* d_out, int out_size) {
    const float* x     = (const float*)d_in[0];
    const void*  ei    = d_in[1];
    const void*  batch = d_in[2];
    const float* W0 = (const float*)d_in[3];  const float* b0 = (const float*)d_in[4];
    const float* W1 = (const float*)d_in[5];  const float* b1 = (const float*)d_in[6];
    const float* W2 = (const float*)d_in[7];  const float* b2 = (const float*)d_in[8];
    const float* W3 = (const float*)d_in[9];  const float* b3 = (const float*)d_in[10];
    const float* Wout = (const float*)d_in[11];
    const float* bout = (const float*)d_in[12];
    float* out = (float*)d_out;

    float *T0;
    __half *Sh, *Uh;
    cudaGetSymbolAddress((void**)&T0, g_T0);
    cudaGetSymbolAddress((void**)&Sh, g_Sh);
    cudaGetSymbolAddress((void**)&Uh, g_Uh);

    const int T = 256;
    const int NB_N   = (N_NODES + T - 1) / T;
    const int NB_E   = (N_EDGES + T - 1) / T;
    const int NB_N32 = (N_NODES * 32 + T - 1) / T;   // warp-per-node grids (25000)
    const int NB_MMA = (N_NODES + 127) / 128;        // 1563
    const int NB_POOL = N_NODES / 8;                 // 25000, exact

    // graph prep: 3 launches (single-pass capacity CSR)
    init_kernel<<<NB_N, T>>>(ei);
    fill_kernel<<<NB_E, T>>>(ei);
    dinv_xs_kernel<<<NB_N, T>>>(x);

    // Layer 0 (8 -> 64, tanh): warp-per-node aggregate, scalar GEMM + act.
    agg0_kernel<<<NB_N32, T>>>();
    gemm0_kernel<<<(N_NODES + 15) / 16, T>>>(T0, W0, b0, Sh);

    // Layer 1 (64 -> 64, relu): HMMA GEMM (split-W) then warp-per-node aggregate.
    gemm_mma_kernel<64, 64><<<NB_MMA, 256>>>(Sh, W1, Uh);
    agg_act64_kernel<<<NB_N32, T>>>(Uh, b1, Sh);

    // Layer 2 (64 -> 32, relu).
    gemm_mma_kernel<64, 32><<<NB_MMA, 256>>>(Sh, W2, Uh);
    agg_act32_kernel<<<NB_N32, T>>>(Uh, b2, Sh);

    // Layer 3 (32 -> 32, relu) + pooling with block-segmented reduction.
    gemm_mma_kernel<32, 32><<<NB_MMA, 256>>>(Sh, W3, Uh);
    agg_pool_kernel<<<NB_POOL, 256>>>(Uh, b3, batch);

    final_kernel<<<(N_GRAPHS * 10 + T - 1) / T, T>>>(Wout, bout, out);
}

// round 17
// speedup vs baseline: 1.1636x; 1.1636x over previous
#include <cuda_runtime.h>
#include <cuda_fp16.h>

#define N_NODES   200000
#define N_EDGES   3200000
#define N_GRAPHS  1024
#define CAP       64          // fixed CSR capacity per node; P(deg>=64) ~ 1e-19

#define W1_OFF 0
#define W2_OFF 4096
#define W3_OFF 6144
#define W_TOTAL 7168

// ---------------- scratch (static device globals) ---------------------------
__device__ __half g_Sh[N_NODES * 64];   // scaled activations S = h * dinv (fp16)
__device__ __half g_Uh[N_NODES * 64];   // gemm outputs (messages, fp16)
__device__ float  g_T0[N_NODES * 8];    // layer-0 aggregated input (fp32)
__device__ float  g_xs[N_NODES * 8];    // x * dinv
__device__ int    g_cur[N_NODES];       // per-node edge count (atomic cursor)
__device__ int    g_csr[N_NODES * CAP]; // fixed-capacity adjacency (src per slot)
__device__ float  g_dinv[N_NODES];
__device__ __half g_Whi[W_TOTAL];       // fp16 hi parts of W1|W2|W3
__device__ __half g_Wlo[W_TOTAL];       // fp16 lo residuals
__device__ float  g_gmax[N_GRAPHS * 32];
__device__ float  g_gsum[N_GRAPHS * 32];
__device__ float  g_cnt[N_GRAPHS];
__device__ int    g_idx64;

// ---------------- prep kernels ----------------------------------------------

__global__ void init_kernel(const void* __restrict__ ei) {
    int i = blockIdx.x * blockDim.x + threadIdx.x;
    if (i == 0) {
        const long long* p = (const long long*)ei;
        int ok = 1;
#pragma unroll
        for (int k = 0; k < 16; k++) {
            long long v = p[k];
            if (v < 0 || v >= N_NODES) ok = 0;
        }
        g_idx64 = ok;
    }
    if (i < N_NODES) g_cur[i] = 0;
    if (i < N_GRAPHS * 32) { g_gmax[i] = 0.0f; g_gsum[i] = 0.0f; }
    if (i < N_GRAPHS) g_cnt[i] = 0.0f;
}

// Single-pass CSR build: count + place in one kernel.
__global__ void fill_kernel(const void* __restrict__ ei) {
    int e = blockIdx.x * blockDim.x + threadIdx.x;
    if (e >= N_EDGES) return;
    int s, d;
    if (g_idx64) {
        const long long* p = (const long long*)ei;
        s = (int)p[e]; d = (int)p[N_EDGES + e];
    } else {
        const int* p = (const int*)ei;
        s = p[e]; d = p[N_EDGES + e];
    }
    int pos = atomicAdd(&g_cur[d], 1);
    if (pos < CAP) g_csr[d * CAP + pos] = s;
}

// dinv = rsqrt(deg+1); xs = x * dinv.
__global__ void dinv_xs_kernel(const float* __restrict__ x) {
    int i = blockIdx.x * blockDim.x + threadIdx.x;
    if (i >= N_NODES) return;
    float dv = rsqrtf((float)(g_cur[i] + 1));
    g_dinv[i] = dv;
    float4 v0 = *(const float4*)(x + (size_t)i * 8);
    float4 v1 = *(const float4*)(x + (size_t)i * 8 + 4);
    v0.x *= dv; v0.y *= dv; v0.z *= dv; v0.w *= dv;
    v1.x *= dv; v1.y *= dv; v1.z *= dv; v1.w *= dv;
    *(float4*)(g_xs + (size_t)i * 8) = v0;
    *(float4*)(g_xs + (size_t)i * 8 + 4) = v1;
}

// Precompute split-precision weights: W = Whi + Wlo (once, not per GEMM block).
__global__ void wprep_kernel(const float* __restrict__ W1, const float* __restrict__ W2,
                             const float* __restrict__ W3) {
    int i = blockIdx.x * blockDim.x + threadIdx.x;
    if (i >= W_TOTAL) return;
    float w;
    if (i < W2_OFF)      w = W1[i];
    else if (i < W3_OFF) w = W2[i - W2_OFF];
    else                 w = W3[i - W3_OFF];
    __half hi = __float2half_rn(w);
    __half lo = __float2half_rn(w - __half2float(hi));
    g_Whi[i] = hi;
    g_Wlo[i] = lo;
}

// ---------------- layer kernels ---------------------------------------------

// Width-8 input aggregation: 4 lanes/node, float2 per lane (same sector traffic
// as R14's 8-lane version, half the load instructions). Plain per-node loop.
// Grid exact: N_NODES*4 = 3125 * 256.
__global__ void agg0_kernel() {
    int gid  = blockIdx.x * blockDim.x + threadIdx.x;
    int node = gid >> 2;
    int lane = gid & 3;
    const float2* xb = (const float2*)g_xs + lane;
    float2 a0 = __ldg(xb + (size_t)node * 4);
    float2 a1 = make_float2(0.f, 0.f), a2 = a1, a3 = a1;
    int dg = g_cur[node]; if (dg > CAP) dg = CAP;
    const int* crow = g_csr + node * CAP;
    int i = 0;
    for (; i + 4 <= dg; i += 4) {
        int s0 = __ldg(crow + i);
        int s1 = __ldg(crow + i + 1);
        int s2 = __ldg(crow + i + 2);
        int s3 = __ldg(crow + i + 3);
        float2 f0 = __ldg(xb + (size_t)s0 * 4);
        float2 f1 = __ldg(xb + (size_t)s1 * 4);
        float2 f2 = __ldg(xb + (size_t)s2 * 4);
        float2 f3 = __ldg(xb + (size_t)s3 * 4);
        a0.x += f0.x; a0.y += f0.y;
        a1.x += f1.x; a1.y += f1.y;
        a2.x += f2.x; a2.y += f2.y;
        a3.x += f3.x; a3.y += f3.y;
    }
    for (; i < dg; i++) {
        int s0 = __ldg(crow + i);
        float2 f0 = __ldg(xb + (size_t)s0 * 4);
        a0.x += f0.x; a0.y += f0.y;
    }
    float dv = g_dinv[node];
    float2 r;
    r.x = ((a0.x + a1.x) + (a2.x + a3.x)) * dv;
    r.y = ((a0.y + a1.y) + (a2.y + a3.y)) * dv;
    ((float2*)g_T0)[(size_t)node * 4 + lane] = r;
}

// Layer-0 scalar GEMM (K=8): out = tanh(t0 @ W0 + b) * dinv, fp16 out.
__global__ void gemm0_kernel(const float* __restrict__ in, const float* __restrict__ W,
                             const float* __restrict__ b, __half* __restrict__ outh) {
    const int K = 8, NO = 64, TPN = 16, NPB = 16;
    __shared__ float sW[K * NO];
    __shared__ float sIn[NPB * K];
    for (int i = threadIdx.x; i < K * NO; i += 256) sW[i] = W[i];
    int node0 = blockIdx.x * NPB;
    for (int i = threadIdx.x; i < NPB * K; i += 256) {
        int n = node0 + i / K;
        sIn[i] = (n < N_NODES) ? in[(size_t)n * K + (i % K)] : 0.0f;
    }
    __syncthreads();
    int node = node0 + threadIdx.x / TPN;
    int oc   = (threadIdx.x % TPN) * 4;
    if (node >= N_NODES) return;
    const float* r = sIn + (threadIdx.x / TPN) * K;
    float a0 = 0.f, a1 = 0.f, a2 = 0.f, a3 = 0.f;
#pragma unroll
    for (int k = 0; k < K; k++) {
        float xv = r[k];
        float4 w = *(const float4*)(sW + k * NO + oc);
        a0 += xv * w.x; a1 += xv * w.y; a2 += xv * w.z; a3 += xv * w.w;
    }
    float dv = g_dinv[node];
    float4 bb = *(const float4*)(b + oc);
    a0 = tanhf(a0 + bb.x) * dv;
    a1 = tanhf(a1 + bb.y) * dv;
    a2 = tanhf(a2 + bb.z) * dv;
    a3 = tanhf(a3 + bb.w) * dv;
    __half2 h01 = __floats2half2_rn(a0, a1);
    __half2 h23 = __floats2half2_rn(a2, a3);
    uint2 st;
    st.x = *(unsigned int*)&h01;
    st.y = *(unsigned int*)&h23;
    *(uint2*)(outh + (size_t)node * NO + oc) = st;
}

// HMMA GEMM: out = in @ W, fp16 in/out, fp32 accum, precomputed split-W hi/lo.
template <int K, int NO>
__global__ void gemm_mma_kernel(const __half* __restrict__ in,
                                const __half* __restrict__ whi,
                                const __half* __restrict__ wlo,
                                __half* __restrict__ outh) {
    const int LDA = K + 8;
    const int LDB = NO + 8;
    const int KC = K / 16;
    const int NT = NO / 8;
    const int NPB = 128;
    __shared__ __half sA[NPB * LDA];
    __shared__ __half sBhi[K * LDB];
    __shared__ __half sBlo[K * LDB];
    int tid = threadIdx.x;
    int node0 = blockIdx.x * NPB;
    int nvalid = N_NODES - node0;
    if (nvalid > NPB) nvalid = NPB;

    for (int i = tid; i < NPB * (K / 8); i += 256) {
        int r = i / (K / 8), c = i % (K / 8);
        uint4 v = make_uint4(0u, 0u, 0u, 0u);
        if (r < nvalid)
            v = ((const uint4*)(in + (size_t)node0 * K))[i];
        *(uint4*)(sA + r * LDA + c * 8) = v;
    }
    for (int i = tid; i < K * NO / 2; i += 256) {
        int k = i / (NO / 2), n2 = i % (NO / 2);
        ((__half2*)(sBhi + k * LDB))[n2] = ((const __half2*)whi)[i];
        ((__half2*)(sBlo + k * LDB))[n2] = ((const __half2*)wlo)[i];
    }
    __syncthreads();

    int warp = tid >> 5, lane = tid & 31;
    float acc[NT][4];
#pragma unroll
    for (int nt = 0; nt < NT; nt++)
#pragma unroll
        for (int j = 0; j < 4; j++) acc[nt][j] = 0.0f;

    int a_row = warp * 16 + (lane & 15);
    int a_col = (lane >> 4) * 8;
    int b_r   = lane & 7;
    int b_m   = lane >> 3;

#pragma unroll
    for (int kc = 0; kc < KC; kc++) {
        unsigned a0, a1, a2, a3;
        {
            unsigned addr = (unsigned)__cvta_generic_to_shared(
                sA + a_row * LDA + kc * 16 + a_col);
            asm volatile("ldmatrix.sync.aligned.m8n8.x4.shared.b16 {%0,%1,%2,%3}, [%4];"
                         : "=r"(a0), "=r"(a1), "=r"(a2), "=r"(a3) : "r"(addr));
        }
        int krow = kc * 16 + b_r + ((b_m & 1) ? 8 : 0);
#pragma unroll
        for (int nt = 0; nt < NT; nt += 2) {
            int ncol = (nt + ((b_m >> 1) & 1)) * 8;
            unsigned b0, b1, b2, b3;
            {
                unsigned addr = (unsigned)__cvta_generic_to_shared(
                    sBhi + krow * LDB + ncol);
                asm volatile("ldmatrix.sync.aligned.m8n8.x4.trans.shared.b16 {%0,%1,%2,%3}, [%4];"
                             : "=r"(b0), "=r"(b1), "=r"(b2), "=r"(b3) : "r"(addr));
            }
            asm volatile("mma.sync.aligned.m16n8k16.row.col.f32.f16.f16.f32 "
                         "{%0,%1,%2,%3}, {%4,%5,%6,%7}, {%8,%9}, {%0,%1,%2,%3};"
                         : "+f"(acc[nt][0]), "+f"(acc[nt][1]), "+f"(acc[nt][2]), "+f"(acc[nt][3])
                         : "r"(a0), "r"(a1), "r"(a2), "r"(a3), "r"(b0), "r"(b1));
            asm volatile("mma.sync.aligned.m16n8k16.row.col.f32.f16.f16.f32 "
                         "{%0,%1,%2,%3}, {%4,%5,%6,%7}, {%8,%9}, {%0,%1,%2,%3};"
                         : "+f"(acc[nt+1][0]), "+f"(acc[nt+1][1]), "+f"(acc[nt+1][2]), "+f"(acc[nt+1][3])
                         : "r"(a0), "r"(a1), "r"(a2), "r"(a3), "r"(b2), "r"(b3));
            {
                unsigned addr = (unsigned)__cvta_generic_to_shared(
                    sBlo + krow * LDB + ncol);
                asm volatile("ldmatrix.sync.aligned.m8n8.x4.trans.shared.b16 {%0,%1,%2,%3}, [%4];"
                             : "=r"(b0), "=r"(b1), "=r"(b2), "=r"(b3) : "r"(addr));
            }
            asm volatile("mma.sync.aligned.m16n8k16.row.col.f32.f16.f16.f32 "
                         "{%0,%1,%2,%3}, {%4,%5,%6,%7}, {%8,%9}, {%0,%1,%2,%3};"
                         : "+f"(acc[nt][0]), "+f"(acc[nt][1]), "+f"(acc[nt][2]), "+f"(acc[nt][3])
                         : "r"(a0), "r"(a1), "r"(a2), "r"(a3), "r"(b0), "r"(b1));
            asm volatile("mma.sync.aligned.m16n8k16.row.col.f32.f16.f16.f32 "
                         "{%0,%1,%2,%3}, {%4,%5,%6,%7}, {%8,%9}, {%0,%1,%2,%3};"
                         : "+f"(acc[nt+1][0]), "+f"(acc[nt+1][1]), "+f"(acc[nt+1][2]), "+f"(acc[nt+1][3])
                         : "r"(a0), "r"(a1), "r"(a2), "r"(a3), "r"(b2), "r"(b3));
        }
    }

    int r0 = node0 + warp * 16 + (lane >> 2);
    int cbase = (lane & 3) * 2;
#pragma unroll
    for (int nt = 0; nt < NT; nt++) {
        int c = nt * 8 + cbase;
        if (r0 < N_NODES)
            *(__half2*)(outh + (size_t)r0 * NO + c) = __floats2half2_rn(acc[nt][0], acc[nt][1]);
        if (r0 + 8 < N_NODES)
            *(__half2*)(outh + (size_t)(r0 + 8) * NO + c) = __floats2half2_rn(acc[nt][2], acc[nt][3]);
    }
}

// Aggregation of fp16 messages + epilogue (fp32 accumulate), NON-pool layers.
// TPN lanes per node, each lane one half2. 4-way unroll. (R14-proven layout.)
template <int NO, int TPN>
__global__ void agg_act_kernel(const __half* __restrict__ u, const float* __restrict__ b,
                               __half* __restrict__ out) {
    static_assert(NO == TPN * 2, "one half2 per lane");
    int gid  = blockIdx.x * blockDim.x + threadIdx.x;
    int node = gid / TPN;
    int lane = gid % TPN;
    if (node >= N_NODES) return;
    const __half2* base = (const __half2*)u + lane;
    const size_t rowstride = TPN;
    float2 a0, a1, a2, a3;
    {
        float2 f = __half22float2(__ldg(base + (size_t)node * rowstride));
        a0 = f;
        a1 = make_float2(0.f, 0.f); a2 = a1; a3 = a1;
    }
    int dg = g_cur[node]; if (dg > CAP) dg = CAP;
    const int* crow = g_csr + node * CAP;
    int i = 0;
    for (; i + 4 <= dg; i += 4) {
        int s0 = __ldg(crow + i);
        int s1 = __ldg(crow + i + 1);
        int s2 = __ldg(crow + i + 2);
        int s3 = __ldg(crow + i + 3);
        float2 f0 = __half22float2(__ldg(base + (size_t)s0 * rowstride));
        float2 f1 = __half22float2(__ldg(base + (size_t)s1 * rowstride));
        float2 f2 = __half22float2(__ldg(base + (size_t)s2 * rowstride));
        float2 f3 = __half22float2(__ldg(base + (size_t)s3 * rowstride));
        a0.x += f0.x; a0.y += f0.y;
        a1.x += f1.x; a1.y += f1.y;
        a2.x += f2.x; a2.y += f2.y;
        a3.x += f3.x; a3.y += f3.y;
    }
    for (; i < dg; i++) {
        int s0 = __ldg(crow + i);
        float2 f0 = __half22float2(__ldg(base + (size_t)s0 * rowstride));
        a0.x += f0.x; a0.y += f0.y;
    }
    float sx = (a0.x + a1.x) + (a2.x + a3.x);
    float sy = (a0.y + a1.y) + (a2.y + a3.y);
    float dv = g_dinv[node];
    float2 bb = *(const float2*)(b + lane * 2);
    float vx = fmaxf(fmaf(dv, sx, bb.x), 0.0f);
    float vy = fmaxf(fmaf(dv, sy, bb.y), 0.0f);
    __half2 h = __floats2half2_rn(vx * dv, vy * dv);
    ((__half2*)out)[(size_t)node * rowstride + lane] = h;
}

// Layer-3 aggregation + pooling with block-level segmented reduction.
// 256 threads = 16 nodes x 16 lanes; batch sorted -> ~1 segment per block.
__global__ void agg_pool_kernel(const __half* __restrict__ u, const float* __restrict__ b,
                                const void* __restrict__ batch) {
    __shared__ float smax[16][33];
    __shared__ float ssum[16][33];
    __shared__ int   sg[16];
    int tid  = threadIdx.x;
    int nl   = tid >> 4;
    int lane = tid & 15;
    int node = blockIdx.x * 16 + nl;

    const __half2* base = (const __half2*)u + lane;
    const size_t rowstride = 16;
    float2 a0, a1, a2, a3;
    {
        float2 f = __half22float2(__ldg(base + (size_t)node * rowstride));
        a0 = f;
        a1 = make_float2(0.f, 0.f); a2 = a1; a3 = a1;
    }
    int dg = g_cur[node]; if (dg > CAP) dg = CAP;
    const int* crow = g_csr + node * CAP;
    int i = 0;
    for (; i + 4 <= dg; i += 4) {
        int s0 = __ldg(crow + i);
        int s1 = __ldg(crow + i + 1);
        int s2 = __ldg(crow + i + 2);
        int s3 = __ldg(crow + i + 3);
        float2 f0 = __half22float2(__ldg(base + (size_t)s0 * rowstride));
        float2 f1 = __half22float2(__ldg(base + (size_t)s1 * rowstride));
        float2 f2 = __half22float2(__ldg(base + (size_t)s2 * rowstride));
        float2 f3 = __half22float2(__ldg(base + (size_t)s3 * rowstride));
        a0.x += f0.x; a0.y += f0.y;
        a1.x += f1.x; a1.y += f1.y;
        a2.x += f2.x; a2.y += f2.y;
        a3.x += f3.x; a3.y += f3.y;
    }
    for (; i < dg; i++) {
        int s0 = __ldg(crow + i);
        float2 f0 = __half22float2(__ldg(base + (size_t)s0 * rowstride));
        a0.x += f0.x; a0.y += f0.y;
    }
    float sx = (a0.x + a1.x) + (a2.x + a3.x);
    float sy = (a0.y + a1.y) + (a2.y + a3.y);
    float dv = g_dinv[node];
    float2 bb = *(const float2*)(b + lane * 2);
    float vx = fmaxf(fmaf(dv, sx, bb.x), 0.0f);
    float vy = fmaxf(fmaf(dv, sy, bb.y), 0.0f);

    smax[nl][lane * 2]     = vx;
    smax[nl][lane * 2 + 1] = vy;
    ssum[nl][lane * 2]     = vx;
    ssum[nl][lane * 2 + 1] = vy;
    if (lane == 0) {
        int g;
        if (g_idx64) g = (int)((const long long*)batch)[node];
        else         g = ((const int*)batch)[node];
        sg[nl] = g;
    }
    __syncthreads();

    if (tid < 32) {
        int curg = sg[0];
        float cm = smax[0][tid];
        float cs = ssum[0][tid];
#pragma unroll
        for (int k = 1; k < 16; k++) {
            int gi = sg[k];
            float m = smax[k][tid];
            float s = ssum[k][tid];
            if (gi != curg) {
                atomicMax((int*)&g_gmax[curg * 32 + tid], __float_as_int(cm));
                atomicAdd(&g_gsum[curg * 32 + tid], cs);
                curg = gi; cm = m; cs = s;
            } else {
                cm = fmaxf(cm, m);
                cs += s;
            }
        }
        atomicMax((int*)&g_gmax[curg * 32 + tid], __float_as_int(cm));
        atomicAdd(&g_gsum[curg * 32 + tid], cs);
    } else if (tid == 32) {
        int curg = sg[0];
        float c = 1.0f;
#pragma unroll
        for (int k = 1; k < 16; k++) {
            if (sg[k] != curg) {
                atomicAdd(&g_cnt[curg], c);
                curg = sg[k]; c = 1.0f;
            } else c += 1.0f;
        }
        atomicAdd(&g_cnt[curg], c);
    }
}

__global__ void final_kernel(const float* __restrict__ Wout, const float* __restrict__ bout,
                             float* __restrict__ out) {
    int idx = blockIdx.x * blockDim.x + threadIdx.x;
    if (idx >= N_GRAPHS * 10) return;
    int g = idx / 10, o = idx % 10;
    float inv = 1.0f / fmaxf(g_cnt[g], 1.0f);
    float s = bout[o];
#pragma unroll
    for (int f = 0; f < 32; f++) s = fmaf(g_gmax[g * 32 + f], Wout[f * 10 + o], s);
#pragma unroll
    for (int f = 0; f < 32; f++) s = fmaf(g_gsum[g * 32 + f] * inv, Wout[(32 + f) * 10 + o], s);
    out[idx] = s;
}

// ---------------- launch -----------------------------------------------------

extern "C" void kernel_launch(void* const* d_in, const int* in_sizes, int n_in,
                              void* d_out, int out_size) {
    const float* x     = (const float*)d_in[0];
    const void*  ei    = d_in[1];
    const void*  batch = d_in[2];
    const float* W0 = (const float*)d_in[3];  const float* b0 = (const float*)d_in[4];
    const float* W1 = (const float*)d_in[5];  const float* b1 = (const float*)d_in[6];
    const float* W2 = (const float*)d_in[7];  const float* b2 = (const float*)d_in[8];
    const float* W3 = (const float*)d_in[9];  const float* b3 = (const float*)d_in[10];
    const float* Wout = (const float*)d_in[11];
    const float* bout = (const float*)d_in[12];
    float* out = (float*)d_out;

    float *T0;
    __half *Sh, *Uh, *Whi, *Wlo;
    cudaGetSymbolAddress((void**)&T0, g_T0);
    cudaGetSymbolAddress((void**)&Sh, g_Sh);
    cudaGetSymbolAddress((void**)&Uh, g_Uh);
    cudaGetSymbolAddress((void**)&Whi, g_Whi);
    cudaGetSymbolAddress((void**)&Wlo, g_Wlo);

    const int T = 256;
    const int NB_N   = (N_NODES + T - 1) / T;
    const int NB_E   = (N_EDGES + T - 1) / T;
    const int NB_N4  = N_NODES * 4 / T;              // 3125, exact
    const int NB_N16 = (N_NODES * 16 + T - 1) / T;
    const int NB_N32 = (N_NODES * 32 + T - 1) / T;
    const int NB_MMA = (N_NODES + 127) / 128;        // 1563
    const int NB_POOL = N_NODES / 16;                // 12500, exact

    // graph prep: 3 launches (single-pass capacity CSR)
    init_kernel<<<NB_N, T>>>(ei);
    fill_kernel<<<NB_E, T>>>(ei);
    dinv_xs_kernel<<<NB_N, T>>>(x);

    // Layer 0 (8 -> 64, tanh): 4-lane float2 aggregate (profiled slot), GEMM + act.
    agg0_kernel<<<NB_N4, T>>>();
    gemm0_kernel<<<(N_NODES + 15) / 16, T>>>(T0, W0, b0, Sh);

    // Precompute split-precision weights once.
    wprep_kernel<<<(W_TOTAL + T - 1) / T, T>>>(W1, W2, W3);

    // Layer 1 (64 -> 64, relu): HMMA GEMM then aggregate.
    gemm_mma_kernel<64, 64><<<NB_MMA, 256>>>(Sh, Whi + W1_OFF, Wlo + W1_OFF, Uh);
    agg_act_kernel<64, 32><<<NB_N32, T>>>(Uh, b1, Sh);

    // Layer 2 (64 -> 32, relu).
    gemm_mma_kernel<64, 32><<<NB_MMA, 256>>>(Sh, Whi + W2_OFF, Wlo + W2_OFF, Uh);
    agg_act_kernel<32, 16><<<NB_N16, T>>>(Uh, b2, Sh);

    // Layer 3 (32 -> 32, relu) + pooling with block-segmented reduction.
    gemm_mma_kernel<32, 32><<<NB_MMA, 256>>>(Sh, Whi + W3_OFF, Wlo + W3_OFF, Uh);
    agg_pool_kernel<<<NB_POOL, 256>>>(Uh, b3, batch);

    final_kernel<<<(N_GRAPHS * 10 + T - 1) / T, T>>>(Wout, bout, out);
}